// round 14
// baseline (speedup 1.0000x reference)
#include <cuda_runtime.h>
#include <cuda_bf16.h>
#include <math.h>

#define Bb 16
#define Ff 1024
#define Hh 16
#define Dd 64
#define Ll 8192
#define HD 1024        // H*D
#define ROWS 64        // rows per chunk in fused copy kernels
#define CPB (Ll / ROWS) // 128 chunks per batch
#define FCH 64         // proj f-chunks (each 16 wide)
#define OCH 64         // outproj hd-chunks (each 16 wide)

// Output layout: y [B,F] | kv_key [B,L,H,D] | kv_value [B,L,H,D] | new_idx [B]
#define KV_ELEMS ((size_t)Bb * Ll * HD)
#define OFF_Y   ((size_t)0)
#define OFF_K   ((size_t)(Bb * Ff))
#define OFF_V   (OFF_K + KV_ELEMS)
#define OFF_IDX (OFF_V + KV_ELEMS)

// Scratch (device globals)
__device__ __align__(256) float g_qkv[3 * Bb * HD];
__device__ __align__(256) float g_proj_partial[3 * FCH * Bb * HD];      // 12 MB (L2-resident)
__device__ __align__(256) float g_logits[(size_t)Bb * Hh * Ll];         // 8 MB
__device__ __align__(256) float2 g_cstat[Bb * Hh * CPB];                // 256 KB
__device__ __align__(256) float g_av_part[(size_t)Bb * Hh * CPB * Dd];  // 8 MB
__device__ __align__(256) float g_out_partial[OCH * Bb * Ff];           // 4 MB (L2-resident)

static __device__ __forceinline__ float bf16r(float v) {
    return __bfloat162float(__float2bfloat16(v));
}

// Packed bf16 round of two floats (exact expansion via bit ops)
static __device__ __forceinline__ void bf16r2(float a, float b, float& ra, float& rb) {
    __nv_bfloat162 t = __floats2bfloat162_rn(a, b);
    unsigned u = *reinterpret_cast<unsigned*>(&t);
    ra = __uint_as_float(u << 16);
    rb = __uint_as_float(u & 0xffff0000u);
}

// ---------------------------------------------------------------------------
// K1: QKV projection partials: 192 blocks = 3 proj x 64 f-chunks (16 wide)
// ---------------------------------------------------------------------------
__global__ __launch_bounds__(256) void proj_partial_kernel(const float* __restrict__ x,
                                                           const float* __restrict__ Wq,
                                                           const float* __restrict__ Wk,
                                                           const float* __restrict__ Wv) {
    cudaTriggerProgrammaticLaunchCompletion();   // fire early: K2 presync + K3 deads overlap
    int blk = blockIdx.x;
    int p  = blk / FCH;
    int fc = blk - p * FCH;
    const float* W = (p == 0) ? Wq : (p == 1) ? Wk : Wv;
    int tid = threadIdx.x;

    __shared__ float xs[Bb][Ff / FCH];   // 16 x 16
    if (tid < Bb * 16) {
        int b = tid >> 4, f = tid & 15;
        xs[b][f] = x[b * Ff + fc * 16 + f];
    }
    __syncthreads();

    float4 acc[Bb];
#pragma unroll
    for (int b = 0; b < Bb; b++) acc[b] = make_float4(0.f, 0.f, 0.f, 0.f);

    const float4* Wp = (const float4*)(W + (size_t)(fc * 16) * HD) + tid;
#pragma unroll 4
    for (int f = 0; f < 16; f++) {
        float4 w = Wp[(size_t)f * 256];
#pragma unroll
        for (int b = 0; b < Bb; b++) {
            float xv = xs[b][f];
            acc[b].x = fmaf(xv, w.x, acc[b].x);
            acc[b].y = fmaf(xv, w.y, acc[b].y);
            acc[b].z = fmaf(xv, w.z, acc[b].z);
            acc[b].w = fmaf(xv, w.w, acc[b].w);
        }
    }
#pragma unroll
    for (int b = 0; b < Bb; b++)
        ((float4*)(g_proj_partial + ((size_t)(p * FCH + fc) * Bb + b) * HD))[tid] = acc[b];
}

// ---------------------------------------------------------------------------
// K2: reduce proj partials; also writes new_idx output
// ---------------------------------------------------------------------------
__global__ __launch_bounds__(256) void proj_reduce_kernel(const float* __restrict__ bq,
                                                          const float* __restrict__ bk,
                                                          const float* __restrict__ bv,
                                                          const int* __restrict__ kv_idx,
                                                          float* __restrict__ out) {
    cudaTriggerProgrammaticLaunchCompletion();   // K3 dead chunks need nothing from us
    // new_idx depends only on inputs — do it pre-sync
    if (blockIdx.x == 0 && threadIdx.x < Bb)
        out[OFF_IDX + threadIdx.x] = (float)(kv_idx[threadIdx.x] + 1);

    cudaGridDependencySynchronize();

    int i = blockIdx.x * 256 + threadIdx.x;   // < 3*B*HD = 49152
    if (i < 3 * Bb * HD) {
        int p = i / (Bb * HD);
        int rem = i - p * (Bb * HD);
        int b = rem / HD, o = rem - b * HD;
        float s = ((p == 0) ? bq : (p == 1) ? bk : bv)[o];
#pragma unroll 8
        for (int c = 0; c < FCH; c++)
            s += g_proj_partial[((size_t)(p * FCH + c) * Bb + b) * HD + o];
        g_qkv[i] = s;
    }
}

// ---------------------------------------------------------------------------
// K3: fused K copy + insert + logits + per-chunk stats.
// REVERSED chunk order: dead chunks (pure copy, no sync) get the LOWEST block
// indices so they run first — overlapping K1/K2 and the previous drain.
// ---------------------------------------------------------------------------
__global__ __launch_bounds__(256) void copyk_logits_kernel(const float* __restrict__ kvk,
                                                           const int* __restrict__ kv_idx,
                                                           float* __restrict__ out) {
    cudaTriggerProgrammaticLaunchCompletion();   // let K4 launch as our last wave starts
    int blk = blockIdx.x;
    int b = blk >> 7;
    int c = (CPB - 1) - (blk & (CPB - 1));       // reversed
    int l0 = c * ROWS;
    int kvi = kv_idx[b];
    int seq = min(kvi + 1, Ll);
    int idx = kvi & (Ll - 1);
    int tid = threadIdx.x, lane = tid & 31, warp = tid >> 5;
    bool chunk_live = (l0 < seq);

    __shared__ __align__(16) float q_s[HD];
    __shared__ __align__(16) float slog[Hh][ROWS];

    if (chunk_live) {
        cudaGridDependencySynchronize();   // q / k_new from proj
        for (int i = tid; i < HD; i += 256) q_s[i] = bf16r(g_qkv[(size_t)b * HD + i]);
        __syncthreads();
    }

    const float4* knew4 = (const float4*)(g_qkv + (size_t)Bb * HD + (size_t)b * HD);

    bool s3 = (lane & 8) != 0;
    bool s2 = (lane & 4) != 0;
    bool s1 = (lane & 2) != 0;
    int h_out = 2 * ((lane >> 1) & 7) + (lane >> 4);

#pragma unroll
    for (int t = 0; t < ROWS / 8; t++) {
        int rl = warp + 8 * t;
        int l = l0 + rl;
        const float4* src = (l == idx) ? knew4
                          : (const float4*)(kvk + ((size_t)b * Ll + l) * HD);
        float4* dst = (float4*)(out + OFF_K + ((size_t)b * Ll + l) * HD);
        float4 v[8];
#pragma unroll
        for (int j = 0; j < 8; j++) v[j] = __ldcs(src + j * 32 + lane);
#pragma unroll
        for (int j = 0; j < 8; j++) __stcs(dst + j * 32 + lane, v[j]);
        if (l < seq) {
            float p[8];
#pragma unroll
            for (int j = 0; j < 8; j++) {
                int h = 2 * j + (lane >> 4);
                const float* qh = q_s + h * Dd + (lane & 15) * 4;
                float r0, r1, r2, r3;
                bf16r2(v[j].x, v[j].y, r0, r1);
                bf16r2(v[j].z, v[j].w, r2, r3);
                p[j] = r0 * qh[0] + r1 * qh[1] + r2 * qh[2] + r3 * qh[3];
            }
            float a0[4];
#pragma unroll
            for (int m = 0; m < 4; m++) {
                float send = s3 ? p[m] : p[m + 4];
                float r = __shfl_xor_sync(0xffffffffu, send, 8, 16);
                float keep = s3 ? p[m + 4] : p[m];
                a0[m] = keep + r;
            }
            float b0[2];
#pragma unroll
            for (int m = 0; m < 2; m++) {
                float send = s2 ? a0[m] : a0[m + 2];
                float r = __shfl_xor_sync(0xffffffffu, send, 4, 16);
                float keep = s2 ? a0[m + 2] : a0[m];
                b0[m] = keep + r;
            }
            {
                float send = s1 ? b0[0] : b0[1];
                float r = __shfl_xor_sync(0xffffffffu, send, 2, 16);
                float keep = s1 ? b0[1] : b0[0];
                b0[0] = keep + r;
            }
            b0[0] += __shfl_xor_sync(0xffffffffu, b0[0], 1, 16);
            if ((lane & 1) == 0) slog[h_out][rl] = b0[0] * 0.125f;
        }
    }

    if (chunk_live) {
        __syncthreads();
        int h = tid >> 4, r4 = tid & 15;
        float4 vv = ((const float4*)slog[h])[r4];
        ((float4*)(g_logits + ((size_t)(b * Hh + h)) * Ll + l0))[r4] = vv;

        int lmax = seq - l0;
        int r = r4 * 4;
        float v0 = (r     < lmax) ? vv.x : -INFINITY;
        float v1 = (r + 1 < lmax) ? vv.y : -INFINITY;
        float v2 = (r + 2 < lmax) ? vv.z : -INFINITY;
        float v3 = (r + 3 < lmax) ? vv.w : -INFINITY;
        float m = fmaxf(fmaxf(v0, v1), fmaxf(v2, v3));
#pragma unroll
        for (int off = 8; off > 0; off >>= 1)
            m = fmaxf(m, __shfl_xor_sync(0xffffffffu, m, off, 16));
        float s = expf(v0 - m) + expf(v1 - m) + expf(v2 - m) + expf(v3 - m);
#pragma unroll
        for (int off = 8; off > 0; off >>= 1)
            s += __shfl_xor_sync(0xffffffffu, s, off, 16);
        if ((lane & 15) == 0)
            g_cstat[(b * Hh + h) * CPB + c] = make_float2(m, s);
    }
}

// ---------------------------------------------------------------------------
// K4: fused V copy + insert + AV partials.
// Reversed chunk order: dead chunks (pure copy, no sync) run first,
// overlapping copyk's drain.
// ---------------------------------------------------------------------------
__global__ __launch_bounds__(256) void copyv_av_kernel(const float* __restrict__ kvv,
                                                       const int* __restrict__ kv_idx,
                                                       float* __restrict__ out) {
    cudaTriggerProgrammaticLaunchCompletion();
    int blk = blockIdx.x;
    int b = blk >> 7;
    int c = (CPB - 1) - (blk & (CPB - 1));       // reversed
    int l0 = c * ROWS;
    int kvi = kv_idx[b];
    int seq = min(kvi + 1, Ll);
    int idx = kvi & (Ll - 1);
    int tid = threadIdx.x, lane = tid & 31, warp = tid >> 5;
    int bh0 = b * Hh;

    __shared__ __align__(16) float prob_s[Hh][ROWS];
    __shared__ __align__(16) float wacc[8][HD];
    __shared__ float sM[Hh], sS[Hh];

    if (l0 >= seq) {
        // Dead chunk: independent of copyk — run without waiting
#pragma unroll
        for (int t = 0; t < ROWS / 8; t++) {
            int l = l0 + warp + 8 * t;
            const float4* src = (const float4*)(kvv + ((size_t)b * Ll + l) * HD);
            float4* dst = (float4*)(out + OFF_V + ((size_t)b * Ll + l) * HD);
            float4 v[8];
#pragma unroll
            for (int j = 0; j < 8; j++) v[j] = __ldcs(src + j * 32 + lane);
#pragma unroll
            for (int j = 0; j < 8; j++) __stcs(dst + j * 32 + lane, v[j]);
        }
        return;
    }

    cudaGridDependencySynchronize();   // logits + cstat from copyk

    {
        int h = tid >> 4, sub = tid & 15;
        int smax = (seq + ROWS - 1) / ROWS;
        const float2* cs = g_cstat + (bh0 + h) * CPB;
        float m = -INFINITY;
        for (int cc = sub; cc < smax; cc += 16) m = fmaxf(m, cs[cc].x);
#pragma unroll
        for (int off = 8; off > 0; off >>= 1)
            m = fmaxf(m, __shfl_xor_sync(0xffffffffu, m, off, 16));
        float s = 0.0f;
        for (int cc = sub; cc < smax; cc += 16) {
            float2 t = cs[cc];
            s += expf(t.x - m) * t.y;
        }
#pragma unroll
        for (int off = 8; off > 0; off >>= 1)
            s += __shfl_xor_sync(0xffffffffu, s, off, 16);
        if (sub == 0) { sM[h] = m; sS[h] = s; }
    }
    __syncthreads();

    {
        int h = tid >> 4, r4 = tid & 15;
        float4 lg4 = ((const float4*)(g_logits + ((size_t)(bh0 + h)) * Ll + l0))[r4];
        float m = sM[h];
        float inv_s = 1.0f / sS[h];
        int r = r4 * 4;
        float4 pv;
        pv.x = (l0 + r     < seq) ? bf16r(expf(lg4.x - m) * inv_s) : 0.0f;
        pv.y = (l0 + r + 1 < seq) ? bf16r(expf(lg4.y - m) * inv_s) : 0.0f;
        pv.z = (l0 + r + 2 < seq) ? bf16r(expf(lg4.z - m) * inv_s) : 0.0f;
        pv.w = (l0 + r + 3 < seq) ? bf16r(expf(lg4.w - m) * inv_s) : 0.0f;
        ((float4*)prob_s[h])[r4] = pv;
    }
    __syncthreads();

    const float4* vnew4 = (const float4*)(g_qkv + (size_t)2 * Bb * HD + (size_t)b * HD);

    float acc[8][4];
#pragma unroll
    for (int j = 0; j < 8; j++)
#pragma unroll
        for (int i = 0; i < 4; i++) acc[j][i] = 0.0f;

#pragma unroll
    for (int t = 0; t < ROWS / 8; t++) {
        int rl = warp + 8 * t;
        int l = l0 + rl;
        const float4* src = (l == idx) ? vnew4
                          : (const float4*)(kvv + ((size_t)b * Ll + l) * HD);
        float4* dst = (float4*)(out + OFF_V + ((size_t)b * Ll + l) * HD);
        float4 v[8];
#pragma unroll
        for (int j = 0; j < 8; j++) v[j] = __ldcs(src + j * 32 + lane);
#pragma unroll
        for (int j = 0; j < 8; j++) __stcs(dst + j * 32 + lane, v[j]);
#pragma unroll
        for (int j = 0; j < 8; j++) {
            int h = 2 * j + (lane >> 4);
            float pb = prob_s[h][rl];
            float r0, r1, r2, r3;
            bf16r2(v[j].x, v[j].y, r0, r1);
            bf16r2(v[j].z, v[j].w, r2, r3);
            acc[j][0] = fmaf(pb, r0, acc[j][0]);
            acc[j][1] = fmaf(pb, r1, acc[j][1]);
            acc[j][2] = fmaf(pb, r2, acc[j][2]);
            acc[j][3] = fmaf(pb, r3, acc[j][3]);
        }
    }

#pragma unroll
    for (int j = 0; j < 8; j++) {
        int h = 2 * j + (lane >> 4);
        int d = (lane & 15) * 4;
#pragma unroll
        for (int i = 0; i < 4; i++)
            wacc[warp][h * Dd + d + i] = acc[j][i];
    }
    __syncthreads();

    for (int i = tid; i < HD; i += 256) {
        float s = 0.0f;
#pragma unroll
        for (int w = 0; w < 8; w++) s += wacc[w][i];
        int h = i >> 6, d = i & 63;
        g_av_part[(((size_t)(bh0 + h)) * CPB + c) * Dd + d] = s;
    }
}

// ---------------------------------------------------------------------------
// K5: outproj partial: 64 blocks; av chunk-reduce fused into staging
// ---------------------------------------------------------------------------
__global__ __launch_bounds__(256) void outproj_partial_kernel(const float* __restrict__ Wo,
                                                              const int* __restrict__ kv_idx) {
    cudaTriggerProgrammaticLaunchCompletion();
    int hc = blockIdx.x;      // 0..63, chunk of 16 hd
    int tid = threadIdx.x;

    cudaGridDependencySynchronize();   // av_part from copyv

    __shared__ float as[Bb][HD / OCH];   // 16 x 16
    if (tid < Bb * 16) {
        int b = tid >> 4, j = tid & 15;
        int hd = hc * 16 + j;
        int bh = b * Hh + (hd >> 6);
        int d = hd & 63;
        int seq = min(kv_idx[b] + 1, Ll);
        int smax = (seq + ROWS - 1) / ROWS;
        const float* src = g_av_part + (size_t)bh * CPB * Dd + d;
        float t = 0.0f;
#pragma unroll 4
        for (int s = 0; s < smax; s++)
            t += src[(size_t)s * Dd];
        as[b][j] = bf16r(t);
    }
    __syncthreads();

    float4 acc[Bb];
#pragma unroll
    for (int b = 0; b < Bb; b++) acc[b] = make_float4(0.f, 0.f, 0.f, 0.f);

    const float4* Wp = (const float4*)(Wo + (size_t)(hc * 16) * Ff) + tid;
#pragma unroll 4
    for (int j = 0; j < 16; j++) {
        float4 w = Wp[(size_t)j * 256];
#pragma unroll
        for (int b = 0; b < Bb; b++) {
            float av = as[b][j];
            acc[b].x = fmaf(av, w.x, acc[b].x);
            acc[b].y = fmaf(av, w.y, acc[b].y);
            acc[b].z = fmaf(av, w.z, acc[b].z);
            acc[b].w = fmaf(av, w.w, acc[b].w);
        }
    }
#pragma unroll
    for (int b = 0; b < Bb; b++)
        ((float4*)(g_out_partial + ((size_t)hc * Bb + b) * Ff))[tid] = acc[b];
}

// ---------------------------------------------------------------------------
// K6: outproj reduce
// ---------------------------------------------------------------------------
__global__ __launch_bounds__(256) void outproj_reduce_kernel(const float* __restrict__ bo,
                                                             float* __restrict__ out) {
    cudaGridDependencySynchronize();
    int i = blockIdx.x * 256 + threadIdx.x;   // < B*F = 16384
    if (i < Bb * Ff) {
        int f = i & (Ff - 1);
        float s = bo[f];
#pragma unroll 8
        for (int c = 0; c < OCH; c++)
            s += g_out_partial[(size_t)c * Bb * Ff + i];
        out[OFF_Y + i] = s;
    }
}

// ---------------------------------------------------------------------------
// Host: PDL-chained launches (kernels 2..6 use programmatic stream serialization)
// ---------------------------------------------------------------------------
template <typename K, typename... Args>
static void launch_pdl(K kernel, int grid, int block, Args... args) {
    cudaLaunchAttribute attr[1];
    attr[0].id = cudaLaunchAttributeProgrammaticStreamSerialization;
    attr[0].val.programmaticStreamSerializationAllowed = 1;
    cudaLaunchConfig_t cfg = {};
    cfg.gridDim = dim3(grid, 1, 1);
    cfg.blockDim = dim3(block, 1, 1);
    cfg.dynamicSmemBytes = 0;
    cfg.stream = 0;
    cfg.attrs = attr;
    cfg.numAttrs = 1;
    cudaLaunchKernelEx(&cfg, kernel, args...);
}

extern "C" void kernel_launch(void* const* d_in, const int* in_sizes, int n_in,
                              void* d_out, int out_size) {
    const float* x    = (const float*)d_in[0];
    const float* kvk  = (const float*)d_in[1];
    const float* kvv  = (const float*)d_in[2];
    const int*   kidx = (const int*)  d_in[3];
    const float* Wq   = (const float*)d_in[4];
    const float* bq   = (const float*)d_in[5];
    const float* Wk   = (const float*)d_in[6];
    const float* bk   = (const float*)d_in[7];
    const float* Wv   = (const float*)d_in[8];
    const float* bv   = (const float*)d_in[9];
    const float* Wo   = (const float*)d_in[10];
    const float* bo   = (const float*)d_in[11];
    float* out = (float*)d_out;

    proj_partial_kernel<<<3 * FCH, 256>>>(x, Wq, Wk, Wv);                       // K1
    launch_pdl(proj_reduce_kernel, 192, 256, bq, bk, bv, kidx, out);            // K2
    launch_pdl(copyk_logits_kernel, Bb * CPB, 256, kvk, kidx, out);             // K3
    launch_pdl(copyv_av_kernel, Bb * CPB, 256, kvv, kidx, out);                 // K4 <- ncu target
    launch_pdl(outproj_partial_kernel, OCH, 256, Wo, kidx);                     // K5
    launch_pdl(outproj_reduce_kernel, 64, 256, bo, out);                        // K6
}

// round 15
// speedup vs baseline: 1.0655x; 1.0655x over previous
#include <cuda_runtime.h>
#include <cuda_bf16.h>
#include <math.h>

#define Bb 16
#define Ff 1024
#define Hh 16
#define Dd 64
#define Ll 8192
#define HD 1024        // H*D
#define ROWS 64        // rows per chunk in fused copy kernels
#define CPB (Ll / ROWS) // 128 chunks per batch
#define FCH 64         // proj f-chunks (each 16 wide)
#define OCH 64         // outproj hd-chunks (each 16 wide)

// Output layout: y [B,F] | kv_key [B,L,H,D] | kv_value [B,L,H,D] | new_idx [B]
#define KV_ELEMS ((size_t)Bb * Ll * HD)
#define OFF_Y   ((size_t)0)
#define OFF_K   ((size_t)(Bb * Ff))
#define OFF_V   (OFF_K + KV_ELEMS)
#define OFF_IDX (OFF_V + KV_ELEMS)

// Scratch (device globals)
__device__ __align__(256) float g_qkv[3 * Bb * HD];
__device__ __align__(256) float g_proj_partial[3 * FCH * Bb * HD];      // 12 MB (L2-resident)
__device__ __align__(256) float g_logits[(size_t)Bb * Hh * Ll];         // 8 MB
__device__ __align__(256) float2 g_cstat[Bb * Hh * CPB];                // 256 KB
__device__ __align__(256) float g_av_part[(size_t)Bb * Hh * CPB * Dd];  // 8 MB
__device__ __align__(256) float g_out_partial[OCH * Bb * Ff];           // 4 MB (L2-resident)

static __device__ __forceinline__ float bf16r(float v) {
    return __bfloat162float(__float2bfloat16(v));
}

// Packed bf16 round of two floats (exact expansion via bit ops)
static __device__ __forceinline__ void bf16r2(float a, float b, float& ra, float& rb) {
    __nv_bfloat162 t = __floats2bfloat162_rn(a, b);
    unsigned u = *reinterpret_cast<unsigned*>(&t);
    ra = __uint_as_float(u << 16);
    rb = __uint_as_float(u & 0xffff0000u);
}

// ---------------------------------------------------------------------------
// K1: QKV projection partials: 192 blocks = 3 proj x 64 f-chunks (16 wide)
// Trigger at start: tiny kernel; K2's pre-sync part and K3's dead chunks
// can overlap safely (they don't read our output).
// ---------------------------------------------------------------------------
__global__ __launch_bounds__(256) void proj_partial_kernel(const float* __restrict__ x,
                                                           const float* __restrict__ Wq,
                                                           const float* __restrict__ Wk,
                                                           const float* __restrict__ Wv) {
    cudaTriggerProgrammaticLaunchCompletion();
    int blk = blockIdx.x;
    int p  = blk / FCH;
    int fc = blk - p * FCH;
    const float* W = (p == 0) ? Wq : (p == 1) ? Wk : Wv;
    int tid = threadIdx.x;

    __shared__ float xs[Bb][Ff / FCH];   // 16 x 16
    if (tid < Bb * 16) {
        int b = tid >> 4, f = tid & 15;
        xs[b][f] = x[b * Ff + fc * 16 + f];
    }
    __syncthreads();

    float4 acc[Bb];
#pragma unroll
    for (int b = 0; b < Bb; b++) acc[b] = make_float4(0.f, 0.f, 0.f, 0.f);

    const float4* Wp = (const float4*)(W + (size_t)(fc * 16) * HD) + tid;
#pragma unroll 4
    for (int f = 0; f < 16; f++) {
        float4 w = Wp[(size_t)f * 256];
#pragma unroll
        for (int b = 0; b < Bb; b++) {
            float xv = xs[b][f];
            acc[b].x = fmaf(xv, w.x, acc[b].x);
            acc[b].y = fmaf(xv, w.y, acc[b].y);
            acc[b].z = fmaf(xv, w.z, acc[b].z);
            acc[b].w = fmaf(xv, w.w, acc[b].w);
        }
    }
#pragma unroll
    for (int b = 0; b < Bb; b++)
        ((float4*)(g_proj_partial + ((size_t)(p * FCH + fc) * Bb + b) * HD))[tid] = acc[b];
}

// ---------------------------------------------------------------------------
// K2: reduce proj partials; also writes new_idx output.
// Trigger at start: tiny kernel; K3's dead chunks don't read g_qkv.
// ---------------------------------------------------------------------------
__global__ __launch_bounds__(256) void proj_reduce_kernel(const float* __restrict__ bq,
                                                          const float* __restrict__ bk,
                                                          const float* __restrict__ bv,
                                                          const int* __restrict__ kv_idx,
                                                          float* __restrict__ out) {
    cudaTriggerProgrammaticLaunchCompletion();
    // new_idx depends only on inputs — do it pre-sync
    if (blockIdx.x == 0 && threadIdx.x < Bb)
        out[OFF_IDX + threadIdx.x] = (float)(kv_idx[threadIdx.x] + 1);

    cudaGridDependencySynchronize();

    int i = blockIdx.x * 256 + threadIdx.x;   // < 3*B*HD = 49152
    if (i < 3 * Bb * HD) {
        int p = i / (Bb * HD);
        int rem = i - p * (Bb * HD);
        int b = rem / HD, o = rem - b * HD;
        float s = ((p == 0) ? bq : (p == 1) ? bk : bv)[o];
#pragma unroll 8
        for (int c = 0; c < FCH; c++)
            s += g_proj_partial[((size_t)(p * FCH + c) * Bb + b) * HD + o];
        g_qkv[i] = s;
    }
}

// ---------------------------------------------------------------------------
// K3: fused K copy + insert + logits + per-chunk stats.
// Natural chunk order; trigger at end (R13-proven config).
// Dead chunks never touch g_qkv -> run pre-sync.
// ---------------------------------------------------------------------------
__global__ __launch_bounds__(256) void copyk_logits_kernel(const float* __restrict__ kvk,
                                                           const int* __restrict__ kv_idx,
                                                           float* __restrict__ out) {
    int blk = blockIdx.x;
    int b = blk >> 7;
    int c = blk & (CPB - 1);
    int l0 = c * ROWS;
    int kvi = kv_idx[b];
    int seq = min(kvi + 1, Ll);
    int idx = kvi & (Ll - 1);
    int tid = threadIdx.x, lane = tid & 31, warp = tid >> 5;
    bool chunk_live = (l0 < seq);

    __shared__ __align__(16) float q_s[HD];
    __shared__ __align__(16) float slog[Hh][ROWS];

    if (chunk_live) {
        cudaGridDependencySynchronize();   // q / k_new from proj
        for (int i = tid; i < HD; i += 256) q_s[i] = bf16r(g_qkv[(size_t)b * HD + i]);
        __syncthreads();
    }

    const float4* knew4 = (const float4*)(g_qkv + (size_t)Bb * HD + (size_t)b * HD);

    bool s3 = (lane & 8) != 0;
    bool s2 = (lane & 4) != 0;
    bool s1 = (lane & 2) != 0;
    int h_out = 2 * ((lane >> 1) & 7) + (lane >> 4);

#pragma unroll
    for (int t = 0; t < ROWS / 8; t++) {
        int rl = warp + 8 * t;
        int l = l0 + rl;
        const float4* src = (l == idx) ? knew4
                          : (const float4*)(kvk + ((size_t)b * Ll + l) * HD);
        float4* dst = (float4*)(out + OFF_K + ((size_t)b * Ll + l) * HD);
        float4 v[8];
#pragma unroll
        for (int j = 0; j < 8; j++) v[j] = __ldcs(src + j * 32 + lane);
#pragma unroll
        for (int j = 0; j < 8; j++) __stcs(dst + j * 32 + lane, v[j]);
        if (l < seq) {
            float p[8];
#pragma unroll
            for (int j = 0; j < 8; j++) {
                int h = 2 * j + (lane >> 4);
                const float* qh = q_s + h * Dd + (lane & 15) * 4;
                float r0, r1, r2, r3;
                bf16r2(v[j].x, v[j].y, r0, r1);
                bf16r2(v[j].z, v[j].w, r2, r3);
                p[j] = r0 * qh[0] + r1 * qh[1] + r2 * qh[2] + r3 * qh[3];
            }
            float a0[4];
#pragma unroll
            for (int m = 0; m < 4; m++) {
                float send = s3 ? p[m] : p[m + 4];
                float r = __shfl_xor_sync(0xffffffffu, send, 8, 16);
                float keep = s3 ? p[m + 4] : p[m];
                a0[m] = keep + r;
            }
            float b0[2];
#pragma unroll
            for (int m = 0; m < 2; m++) {
                float send = s2 ? a0[m] : a0[m + 2];
                float r = __shfl_xor_sync(0xffffffffu, send, 4, 16);
                float keep = s2 ? a0[m + 2] : a0[m];
                b0[m] = keep + r;
            }
            {
                float send = s1 ? b0[0] : b0[1];
                float r = __shfl_xor_sync(0xffffffffu, send, 2, 16);
                float keep = s1 ? b0[1] : b0[0];
                b0[0] = keep + r;
            }
            b0[0] += __shfl_xor_sync(0xffffffffu, b0[0], 1, 16);
            if ((lane & 1) == 0) slog[h_out][rl] = b0[0] * 0.125f;
        }
    }

    if (chunk_live) {
        __syncthreads();
        int h = tid >> 4, r4 = tid & 15;
        float4 vv = ((const float4*)slog[h])[r4];
        ((float4*)(g_logits + ((size_t)(b * Hh + h)) * Ll + l0))[r4] = vv;

        int lmax = seq - l0;
        int r = r4 * 4;
        float v0 = (r     < lmax) ? vv.x : -INFINITY;
        float v1 = (r + 1 < lmax) ? vv.y : -INFINITY;
        float v2 = (r + 2 < lmax) ? vv.z : -INFINITY;
        float v3 = (r + 3 < lmax) ? vv.w : -INFINITY;
        float m = fmaxf(fmaxf(v0, v1), fmaxf(v2, v3));
#pragma unroll
        for (int off = 8; off > 0; off >>= 1)
            m = fmaxf(m, __shfl_xor_sync(0xffffffffu, m, off, 16));
        float s = expf(v0 - m) + expf(v1 - m) + expf(v2 - m) + expf(v3 - m);
#pragma unroll
        for (int off = 8; off > 0; off >>= 1)
            s += __shfl_xor_sync(0xffffffffu, s, off, 16);
        if ((lane & 15) == 0)
            g_cstat[(b * Hh + h) * CPB + c] = make_float2(m, s);
    }
    cudaTriggerProgrammaticLaunchCompletion();
}

// ---------------------------------------------------------------------------
// K4: fused V copy + insert + AV partials.
// Natural chunk order; trigger at end (R13-proven config).
// Dead chunks: pure copy, pre-sync (overlaps copyk's drain via PDL).
// ---------------------------------------------------------------------------
__global__ __launch_bounds__(256) void copyv_av_kernel(const float* __restrict__ kvv,
                                                       const int* __restrict__ kv_idx,
                                                       float* __restrict__ out) {
    int blk = blockIdx.x;
    int b = blk >> 7;
    int c = blk & (CPB - 1);
    int l0 = c * ROWS;
    int kvi = kv_idx[b];
    int seq = min(kvi + 1, Ll);
    int idx = kvi & (Ll - 1);
    int tid = threadIdx.x, lane = tid & 31, warp = tid >> 5;
    int bh0 = b * Hh;

    __shared__ __align__(16) float prob_s[Hh][ROWS];
    __shared__ __align__(16) float wacc[8][HD];
    __shared__ float sM[Hh], sS[Hh];

    if (l0 >= seq) {
        // Dead chunk: independent of copyk — run without waiting
#pragma unroll
        for (int t = 0; t < ROWS / 8; t++) {
            int l = l0 + warp + 8 * t;
            const float4* src = (const float4*)(kvv + ((size_t)b * Ll + l) * HD);
            float4* dst = (float4*)(out + OFF_V + ((size_t)b * Ll + l) * HD);
            float4 v[8];
#pragma unroll
            for (int j = 0; j < 8; j++) v[j] = __ldcs(src + j * 32 + lane);
#pragma unroll
            for (int j = 0; j < 8; j++) __stcs(dst + j * 32 + lane, v[j]);
        }
        cudaTriggerProgrammaticLaunchCompletion();
        return;
    }

    cudaGridDependencySynchronize();   // logits + cstat from copyk

    {
        int h = tid >> 4, sub = tid & 15;
        int smax = (seq + ROWS - 1) / ROWS;
        const float2* cs = g_cstat + (bh0 + h) * CPB;
        float m = -INFINITY;
        for (int cc = sub; cc < smax; cc += 16) m = fmaxf(m, cs[cc].x);
#pragma unroll
        for (int off = 8; off > 0; off >>= 1)
            m = fmaxf(m, __shfl_xor_sync(0xffffffffu, m, off, 16));
        float s = 0.0f;
        for (int cc = sub; cc < smax; cc += 16) {
            float2 t = cs[cc];
            s += expf(t.x - m) * t.y;
        }
#pragma unroll
        for (int off = 8; off > 0; off >>= 1)
            s += __shfl_xor_sync(0xffffffffu, s, off, 16);
        if (sub == 0) { sM[h] = m; sS[h] = s; }
    }
    __syncthreads();

    {
        int h = tid >> 4, r4 = tid & 15;
        float4 lg4 = ((const float4*)(g_logits + ((size_t)(bh0 + h)) * Ll + l0))[r4];
        float m = sM[h];
        float inv_s = 1.0f / sS[h];
        int r = r4 * 4;
        float4 pv;
        pv.x = (l0 + r     < seq) ? bf16r(expf(lg4.x - m) * inv_s) : 0.0f;
        pv.y = (l0 + r + 1 < seq) ? bf16r(expf(lg4.y - m) * inv_s) : 0.0f;
        pv.z = (l0 + r + 2 < seq) ? bf16r(expf(lg4.z - m) * inv_s) : 0.0f;
        pv.w = (l0 + r + 3 < seq) ? bf16r(expf(lg4.w - m) * inv_s) : 0.0f;
        ((float4*)prob_s[h])[r4] = pv;
    }
    __syncthreads();

    const float4* vnew4 = (const float4*)(g_qkv + (size_t)2 * Bb * HD + (size_t)b * HD);

    float acc[8][4];
#pragma unroll
    for (int j = 0; j < 8; j++)
#pragma unroll
        for (int i = 0; i < 4; i++) acc[j][i] = 0.0f;

#pragma unroll
    for (int t = 0; t < ROWS / 8; t++) {
        int rl = warp + 8 * t;
        int l = l0 + rl;
        const float4* src = (l == idx) ? vnew4
                          : (const float4*)(kvv + ((size_t)b * Ll + l) * HD);
        float4* dst = (float4*)(out + OFF_V + ((size_t)b * Ll + l) * HD);
        float4 v[8];
#pragma unroll
        for (int j = 0; j < 8; j++) v[j] = __ldcs(src + j * 32 + lane);
#pragma unroll
        for (int j = 0; j < 8; j++) __stcs(dst + j * 32 + lane, v[j]);
#pragma unroll
        for (int j = 0; j < 8; j++) {
            int h = 2 * j + (lane >> 4);
            float pb = prob_s[h][rl];
            float r0, r1, r2, r3;
            bf16r2(v[j].x, v[j].y, r0, r1);
            bf16r2(v[j].z, v[j].w, r2, r3);
            acc[j][0] = fmaf(pb, r0, acc[j][0]);
            acc[j][1] = fmaf(pb, r1, acc[j][1]);
            acc[j][2] = fmaf(pb, r2, acc[j][2]);
            acc[j][3] = fmaf(pb, r3, acc[j][3]);
        }
    }

#pragma unroll
    for (int j = 0; j < 8; j++) {
        int h = 2 * j + (lane >> 4);
        int d = (lane & 15) * 4;
#pragma unroll
        for (int i = 0; i < 4; i++)
            wacc[warp][h * Dd + d + i] = acc[j][i];
    }
    __syncthreads();

    for (int i = tid; i < HD; i += 256) {
        float s = 0.0f;
#pragma unroll
        for (int w = 0; w < 8; w++) s += wacc[w][i];
        int h = i >> 6, d = i & 63;
        g_av_part[(((size_t)(bh0 + h)) * CPB + c) * Dd + d] = s;
    }
    cudaTriggerProgrammaticLaunchCompletion();
}

// ---------------------------------------------------------------------------
// K5: outproj partial: 64 blocks; av chunk-reduce fused into staging
// ---------------------------------------------------------------------------
__global__ __launch_bounds__(256) void outproj_partial_kernel(const float* __restrict__ Wo,
                                                              const int* __restrict__ kv_idx) {
    int hc = blockIdx.x;      // 0..63, chunk of 16 hd
    int tid = threadIdx.x;

    cudaGridDependencySynchronize();   // av_part from copyv

    __shared__ float as[Bb][HD / OCH];   // 16 x 16
    if (tid < Bb * 16) {
        int b = tid >> 4, j = tid & 15;
        int hd = hc * 16 + j;
        int bh = b * Hh + (hd >> 6);
        int d = hd & 63;
        int seq = min(kv_idx[b] + 1, Ll);
        int smax = (seq + ROWS - 1) / ROWS;
        const float* src = g_av_part + (size_t)bh * CPB * Dd + d;
        float t = 0.0f;
#pragma unroll 4
        for (int s = 0; s < smax; s++)
            t += src[(size_t)s * Dd];
        as[b][j] = bf16r(t);
    }
    __syncthreads();

    float4 acc[Bb];
#pragma unroll
    for (int b = 0; b < Bb; b++) acc[b] = make_float4(0.f, 0.f, 0.f, 0.f);

    const float4* Wp = (const float4*)(Wo + (size_t)(hc * 16) * Ff) + tid;
#pragma unroll 4
    for (int j = 0; j < 16; j++) {
        float4 w = Wp[(size_t)j * 256];
#pragma unroll
        for (int b = 0; b < Bb; b++) {
            float av = as[b][j];
            acc[b].x = fmaf(av, w.x, acc[b].x);
            acc[b].y = fmaf(av, w.y, acc[b].y);
            acc[b].z = fmaf(av, w.z, acc[b].z);
            acc[b].w = fmaf(av, w.w, acc[b].w);
        }
    }
#pragma unroll
    for (int b = 0; b < Bb; b++)
        ((float4*)(g_out_partial + ((size_t)hc * Bb + b) * Ff))[tid] = acc[b];
    cudaTriggerProgrammaticLaunchCompletion();
}

// ---------------------------------------------------------------------------
// K6: outproj reduce
// ---------------------------------------------------------------------------
__global__ __launch_bounds__(256) void outproj_reduce_kernel(const float* __restrict__ bo,
                                                             float* __restrict__ out) {
    cudaGridDependencySynchronize();
    int i = blockIdx.x * 256 + threadIdx.x;   // < B*F = 16384
    if (i < Bb * Ff) {
        int f = i & (Ff - 1);
        float s = bo[f];
#pragma unroll 8
        for (int c = 0; c < OCH; c++)
            s += g_out_partial[(size_t)c * Bb * Ff + i];
        out[OFF_Y + i] = s;
    }
}

// ---------------------------------------------------------------------------
// Host: PDL-chained launches (kernels 2..6 use programmatic stream serialization)
// ---------------------------------------------------------------------------
template <typename K, typename... Args>
static void launch_pdl(K kernel, int grid, int block, Args... args) {
    cudaLaunchAttribute attr[1];
    attr[0].id = cudaLaunchAttributeProgrammaticStreamSerialization;
    attr[0].val.programmaticStreamSerializationAllowed = 1;
    cudaLaunchConfig_t cfg = {};
    cfg.gridDim = dim3(grid, 1, 1);
    cfg.blockDim = dim3(block, 1, 1);
    cfg.dynamicSmemBytes = 0;
    cfg.stream = 0;
    cfg.attrs = attr;
    cfg.numAttrs = 1;
    cudaLaunchKernelEx(&cfg, kernel, args...);
}

extern "C" void kernel_launch(void* const* d_in, const int* in_sizes, int n_in,
                              void* d_out, int out_size) {
    const float* x    = (const float*)d_in[0];
    const float* kvk  = (const float*)d_in[1];
    const float* kvv  = (const float*)d_in[2];
    const int*   kidx = (const int*)  d_in[3];
    const float* Wq   = (const float*)d_in[4];
    const float* bq   = (const float*)d_in[5];
    const float* Wk   = (const float*)d_in[6];
    const float* bk   = (const float*)d_in[7];
    const float* Wv   = (const float*)d_in[8];
    const float* bv   = (const float*)d_in[9];
    const float* Wo   = (const float*)d_in[10];
    const float* bo   = (const float*)d_in[11];
    float* out = (float*)d_out;

    proj_partial_kernel<<<3 * FCH, 256>>>(x, Wq, Wk, Wv);                       // K1
    launch_pdl(proj_reduce_kernel, 192, 256, bq, bk, bv, kidx, out);            // K2
    launch_pdl(copyk_logits_kernel, Bb * CPB, 256, kvk, kidx, out);             // K3
    launch_pdl(copyv_av_kernel, Bb * CPB, 256, kvv, kidx, out);                 // K4 <- ncu target
    launch_pdl(outproj_partial_kernel, OCH, 256, Wo, kidx);                     // K5
    launch_pdl(outproj_reduce_kernel, 64, 256, bo, out);                        // K6
}

// round 16
// speedup vs baseline: 1.0755x; 1.0093x over previous
#include <cuda_runtime.h>
#include <cuda_bf16.h>
#include <math.h>

#define Bb 16
#define Ff 1024
#define Hh 16
#define Dd 64
#define Ll 8192
#define HD 1024        // H*D
#define ROWS 64        // rows per chunk in fused copy kernels
#define CPB (Ll / ROWS) // 128 chunks per batch
#define FCH 64         // proj f-chunks (each 16 wide)
#define OCH 64         // outproj hd-chunks (each 16 wide)

// Output layout: y [B,F] | kv_key [B,L,H,D] | kv_value [B,L,H,D] | new_idx [B]
#define KV_ELEMS ((size_t)Bb * Ll * HD)
#define OFF_Y   ((size_t)0)
#define OFF_K   ((size_t)(Bb * Ff))
#define OFF_V   (OFF_K + KV_ELEMS)
#define OFF_IDX (OFF_V + KV_ELEMS)

// Scratch (device globals)
__device__ __align__(256) float g_qkv[3 * Bb * HD];
__device__ __align__(256) float g_proj_partial[3 * FCH * Bb * HD];      // 12 MB (L2-resident)
__device__ __align__(256) float g_logits[(size_t)Bb * Hh * Ll];         // 8 MB
__device__ __align__(256) float2 g_cstat[Bb * Hh * CPB];                // 256 KB
__device__ __align__(256) float g_av_part[(size_t)Bb * Hh * CPB * Dd];  // 8 MB
__device__ __align__(256) float g_out_partial[OCH * Bb * Ff];           // 4 MB (L2-resident)

static __device__ __forceinline__ float bf16r(float v) {
    return __bfloat162float(__float2bfloat16(v));
}

// Packed bf16 round of two floats (exact expansion via bit ops)
static __device__ __forceinline__ void bf16r2(float a, float b, float& ra, float& rb) {
    __nv_bfloat162 t = __floats2bfloat162_rn(a, b);
    unsigned u = *reinterpret_cast<unsigned*>(&t);
    ra = __uint_as_float(u << 16);
    rb = __uint_as_float(u & 0xffff0000u);
}

// ---------------------------------------------------------------------------
// K1: QKV projection partials: 192 blocks = 3 proj x 64 f-chunks (16 wide)
// ---------------------------------------------------------------------------
__global__ __launch_bounds__(256) void proj_partial_kernel(const float* __restrict__ x,
                                                           const float* __restrict__ Wq,
                                                           const float* __restrict__ Wk,
                                                           const float* __restrict__ Wv) {
    cudaTriggerProgrammaticLaunchCompletion();
    int blk = blockIdx.x;
    int p  = blk / FCH;
    int fc = blk - p * FCH;
    const float* W = (p == 0) ? Wq : (p == 1) ? Wk : Wv;
    int tid = threadIdx.x;

    __shared__ float xs[Bb][Ff / FCH];   // 16 x 16
    if (tid < Bb * 16) {
        int b = tid >> 4, f = tid & 15;
        xs[b][f] = x[b * Ff + fc * 16 + f];
    }
    __syncthreads();

    float4 acc[Bb];
#pragma unroll
    for (int b = 0; b < Bb; b++) acc[b] = make_float4(0.f, 0.f, 0.f, 0.f);

    const float4* Wp = (const float4*)(W + (size_t)(fc * 16) * HD) + tid;
#pragma unroll 4
    for (int f = 0; f < 16; f++) {
        float4 w = Wp[(size_t)f * 256];
#pragma unroll
        for (int b = 0; b < Bb; b++) {
            float xv = xs[b][f];
            acc[b].x = fmaf(xv, w.x, acc[b].x);
            acc[b].y = fmaf(xv, w.y, acc[b].y);
            acc[b].z = fmaf(xv, w.z, acc[b].z);
            acc[b].w = fmaf(xv, w.w, acc[b].w);
        }
    }
#pragma unroll
    for (int b = 0; b < Bb; b++)
        ((float4*)(g_proj_partial + ((size_t)(p * FCH + fc) * Bb + b) * HD))[tid] = acc[b];
}

// ---------------------------------------------------------------------------
// K2: reduce proj partials; also writes new_idx output.
// ---------------------------------------------------------------------------
__global__ __launch_bounds__(256) void proj_reduce_kernel(const float* __restrict__ bq,
                                                          const float* __restrict__ bk,
                                                          const float* __restrict__ bv,
                                                          const int* __restrict__ kv_idx,
                                                          float* __restrict__ out) {
    cudaTriggerProgrammaticLaunchCompletion();
    // new_idx depends only on inputs — do it pre-sync
    if (blockIdx.x == 0 && threadIdx.x < Bb)
        out[OFF_IDX + threadIdx.x] = (float)(kv_idx[threadIdx.x] + 1);

    cudaGridDependencySynchronize();

    int i = blockIdx.x * 256 + threadIdx.x;   // < 3*B*HD = 49152
    if (i < 3 * Bb * HD) {
        int p = i / (Bb * HD);
        int rem = i - p * (Bb * HD);
        int b = rem / HD, o = rem - b * HD;
        float s = ((p == 0) ? bq : (p == 1) ? bk : bv)[o];
#pragma unroll 8
        for (int c = 0; c < FCH; c++)
            s += g_proj_partial[((size_t)(p * FCH + c) * Bb + b) * HD + o];
        g_qkv[i] = s;
    }
}

// ---------------------------------------------------------------------------
// K3: fused K copy + insert + logits + per-chunk stats (R13/R15-proven).
// ---------------------------------------------------------------------------
__global__ __launch_bounds__(256) void copyk_logits_kernel(const float* __restrict__ kvk,
                                                           const int* __restrict__ kv_idx,
                                                           float* __restrict__ out) {
    int blk = blockIdx.x;
    int b = blk >> 7;
    int c = blk & (CPB - 1);
    int l0 = c * ROWS;
    int kvi = kv_idx[b];
    int seq = min(kvi + 1, Ll);
    int idx = kvi & (Ll - 1);
    int tid = threadIdx.x, lane = tid & 31, warp = tid >> 5;
    bool chunk_live = (l0 < seq);

    __shared__ __align__(16) float q_s[HD];
    __shared__ __align__(16) float slog[Hh][ROWS];

    if (chunk_live) {
        cudaGridDependencySynchronize();   // q / k_new from proj
        for (int i = tid; i < HD; i += 256) q_s[i] = bf16r(g_qkv[(size_t)b * HD + i]);
        __syncthreads();
    }

    const float4* knew4 = (const float4*)(g_qkv + (size_t)Bb * HD + (size_t)b * HD);

    bool s3 = (lane & 8) != 0;
    bool s2 = (lane & 4) != 0;
    bool s1 = (lane & 2) != 0;
    int h_out = 2 * ((lane >> 1) & 7) + (lane >> 4);

#pragma unroll
    for (int t = 0; t < ROWS / 8; t++) {
        int rl = warp + 8 * t;
        int l = l0 + rl;
        const float4* src = (l == idx) ? knew4
                          : (const float4*)(kvk + ((size_t)b * Ll + l) * HD);
        float4* dst = (float4*)(out + OFF_K + ((size_t)b * Ll + l) * HD);
        float4 v[8];
#pragma unroll
        for (int j = 0; j < 8; j++) v[j] = __ldcs(src + j * 32 + lane);
#pragma unroll
        for (int j = 0; j < 8; j++) __stcs(dst + j * 32 + lane, v[j]);
        if (l < seq) {
            float p[8];
#pragma unroll
            for (int j = 0; j < 8; j++) {
                int h = 2 * j + (lane >> 4);
                const float* qh = q_s + h * Dd + (lane & 15) * 4;
                float r0, r1, r2, r3;
                bf16r2(v[j].x, v[j].y, r0, r1);
                bf16r2(v[j].z, v[j].w, r2, r3);
                p[j] = r0 * qh[0] + r1 * qh[1] + r2 * qh[2] + r3 * qh[3];
            }
            float a0[4];
#pragma unroll
            for (int m = 0; m < 4; m++) {
                float send = s3 ? p[m] : p[m + 4];
                float r = __shfl_xor_sync(0xffffffffu, send, 8, 16);
                float keep = s3 ? p[m + 4] : p[m];
                a0[m] = keep + r;
            }
            float b0[2];
#pragma unroll
            for (int m = 0; m < 2; m++) {
                float send = s2 ? a0[m] : a0[m + 2];
                float r = __shfl_xor_sync(0xffffffffu, send, 4, 16);
                float keep = s2 ? a0[m + 2] : a0[m];
                b0[m] = keep + r;
            }
            {
                float send = s1 ? b0[0] : b0[1];
                float r = __shfl_xor_sync(0xffffffffu, send, 2, 16);
                float keep = s1 ? b0[1] : b0[0];
                b0[0] = keep + r;
            }
            b0[0] += __shfl_xor_sync(0xffffffffu, b0[0], 1, 16);
            if ((lane & 1) == 0) slog[h_out][rl] = b0[0] * 0.125f;
        }
    }

    if (chunk_live) {
        __syncthreads();
        int h = tid >> 4, r4 = tid & 15;
        float4 vv = ((const float4*)slog[h])[r4];
        ((float4*)(g_logits + ((size_t)(b * Hh + h)) * Ll + l0))[r4] = vv;

        int lmax = seq - l0;
        int r = r4 * 4;
        float v0 = (r     < lmax) ? vv.x : -INFINITY;
        float v1 = (r + 1 < lmax) ? vv.y : -INFINITY;
        float v2 = (r + 2 < lmax) ? vv.z : -INFINITY;
        float v3 = (r + 3 < lmax) ? vv.w : -INFINITY;
        float m = fmaxf(fmaxf(v0, v1), fmaxf(v2, v3));
#pragma unroll
        for (int off = 8; off > 0; off >>= 1)
            m = fmaxf(m, __shfl_xor_sync(0xffffffffu, m, off, 16));
        float s = expf(v0 - m) + expf(v1 - m) + expf(v2 - m) + expf(v3 - m);
#pragma unroll
        for (int off = 8; off > 0; off >>= 1)
            s += __shfl_xor_sync(0xffffffffu, s, off, 16);
        if ((lane & 15) == 0)
            g_cstat[(b * Hh + h) * CPB + c] = make_float2(m, s);
    }
    cudaTriggerProgrammaticLaunchCompletion();
}

// ---------------------------------------------------------------------------
// K4: fused V copy + insert + AV partials (R13/R15-proven).
// ---------------------------------------------------------------------------
__global__ __launch_bounds__(256) void copyv_av_kernel(const float* __restrict__ kvv,
                                                       const int* __restrict__ kv_idx,
                                                       float* __restrict__ out) {
    int blk = blockIdx.x;
    int b = blk >> 7;
    int c = blk & (CPB - 1);
    int l0 = c * ROWS;
    int kvi = kv_idx[b];
    int seq = min(kvi + 1, Ll);
    int idx = kvi & (Ll - 1);
    int tid = threadIdx.x, lane = tid & 31, warp = tid >> 5;
    int bh0 = b * Hh;

    __shared__ __align__(16) float prob_s[Hh][ROWS];
    __shared__ __align__(16) float wacc[8][HD];
    __shared__ float sM[Hh], sS[Hh];

    if (l0 >= seq) {
        // Dead chunk: independent of copyk — run without waiting
#pragma unroll
        for (int t = 0; t < ROWS / 8; t++) {
            int l = l0 + warp + 8 * t;
            const float4* src = (const float4*)(kvv + ((size_t)b * Ll + l) * HD);
            float4* dst = (float4*)(out + OFF_V + ((size_t)b * Ll + l) * HD);
            float4 v[8];
#pragma unroll
            for (int j = 0; j < 8; j++) v[j] = __ldcs(src + j * 32 + lane);
#pragma unroll
            for (int j = 0; j < 8; j++) __stcs(dst + j * 32 + lane, v[j]);
        }
        cudaTriggerProgrammaticLaunchCompletion();
        return;
    }

    cudaGridDependencySynchronize();   // logits + cstat from copyk

    {
        int h = tid >> 4, sub = tid & 15;
        int smax = (seq + ROWS - 1) / ROWS;
        const float2* cs = g_cstat + (bh0 + h) * CPB;
        float m = -INFINITY;
        for (int cc = sub; cc < smax; cc += 16) m = fmaxf(m, cs[cc].x);
#pragma unroll
        for (int off = 8; off > 0; off >>= 1)
            m = fmaxf(m, __shfl_xor_sync(0xffffffffu, m, off, 16));
        float s = 0.0f;
        for (int cc = sub; cc < smax; cc += 16) {
            float2 t = cs[cc];
            s += expf(t.x - m) * t.y;
        }
#pragma unroll
        for (int off = 8; off > 0; off >>= 1)
            s += __shfl_xor_sync(0xffffffffu, s, off, 16);
        if (sub == 0) { sM[h] = m; sS[h] = s; }
    }
    __syncthreads();

    {
        int h = tid >> 4, r4 = tid & 15;
        float4 lg4 = ((const float4*)(g_logits + ((size_t)(bh0 + h)) * Ll + l0))[r4];
        float m = sM[h];
        float inv_s = 1.0f / sS[h];
        int r = r4 * 4;
        float4 pv;
        pv.x = (l0 + r     < seq) ? bf16r(expf(lg4.x - m) * inv_s) : 0.0f;
        pv.y = (l0 + r + 1 < seq) ? bf16r(expf(lg4.y - m) * inv_s) : 0.0f;
        pv.z = (l0 + r + 2 < seq) ? bf16r(expf(lg4.z - m) * inv_s) : 0.0f;
        pv.w = (l0 + r + 3 < seq) ? bf16r(expf(lg4.w - m) * inv_s) : 0.0f;
        ((float4*)prob_s[h])[r4] = pv;
    }
    __syncthreads();

    const float4* vnew4 = (const float4*)(g_qkv + (size_t)2 * Bb * HD + (size_t)b * HD);

    float acc[8][4];
#pragma unroll
    for (int j = 0; j < 8; j++)
#pragma unroll
        for (int i = 0; i < 4; i++) acc[j][i] = 0.0f;

#pragma unroll
    for (int t = 0; t < ROWS / 8; t++) {
        int rl = warp + 8 * t;
        int l = l0 + rl;
        const float4* src = (l == idx) ? vnew4
                          : (const float4*)(kvv + ((size_t)b * Ll + l) * HD);
        float4* dst = (float4*)(out + OFF_V + ((size_t)b * Ll + l) * HD);
        float4 v[8];
#pragma unroll
        for (int j = 0; j < 8; j++) v[j] = __ldcs(src + j * 32 + lane);
#pragma unroll
        for (int j = 0; j < 8; j++) __stcs(dst + j * 32 + lane, v[j]);
#pragma unroll
        for (int j = 0; j < 8; j++) {
            int h = 2 * j + (lane >> 4);
            float pb = prob_s[h][rl];
            float r0, r1, r2, r3;
            bf16r2(v[j].x, v[j].y, r0, r1);
            bf16r2(v[j].z, v[j].w, r2, r3);
            acc[j][0] = fmaf(pb, r0, acc[j][0]);
            acc[j][1] = fmaf(pb, r1, acc[j][1]);
            acc[j][2] = fmaf(pb, r2, acc[j][2]);
            acc[j][3] = fmaf(pb, r3, acc[j][3]);
        }
    }

#pragma unroll
    for (int j = 0; j < 8; j++) {
        int h = 2 * j + (lane >> 4);
        int d = (lane & 15) * 4;
#pragma unroll
        for (int i = 0; i < 4; i++)
            wacc[warp][h * Dd + d + i] = acc[j][i];
    }
    __syncthreads();

    for (int i = tid; i < HD; i += 256) {
        float s = 0.0f;
#pragma unroll
        for (int w = 0; w < 8; w++) s += wacc[w][i];
        int h = i >> 6, d = i & 63;
        g_av_part[(((size_t)(bh0 + h)) * CPB + c) * Dd + d] = s;
    }
    cudaTriggerProgrammaticLaunchCompletion();
}

// ---------------------------------------------------------------------------
// K5: outproj partial: 64 blocks. Wo prefetched into registers PRE-sync
// (input-only, overlaps K4's drain); trigger at start (tiny kernel).
// ---------------------------------------------------------------------------
__global__ __launch_bounds__(256) void outproj_partial_kernel(const float* __restrict__ Wo,
                                                              const int* __restrict__ kv_idx) {
    cudaTriggerProgrammaticLaunchCompletion();
    int hc = blockIdx.x;      // 0..63, chunk of 16 hd
    int tid = threadIdx.x;

    // Pre-sync: prefetch all 16 Wo float4 (no dependency on K4)
    float4 w[16];
    const float4* Wp = (const float4*)(Wo + (size_t)(hc * 16) * Ff) + tid;
#pragma unroll
    for (int j = 0; j < 16; j++) w[j] = __ldg(Wp + (size_t)j * 256);

    cudaGridDependencySynchronize();   // av_part from copyv

    __shared__ float as[Bb][HD / OCH];   // 16 x 16
    if (tid < Bb * 16) {
        int b = tid >> 4, j = tid & 15;
        int hd = hc * 16 + j;
        int bh = b * Hh + (hd >> 6);
        int d = hd & 63;
        int seq = min(kv_idx[b] + 1, Ll);
        int smax = (seq + ROWS - 1) / ROWS;
        const float* src = g_av_part + (size_t)bh * CPB * Dd + d;
        float t = 0.0f;
#pragma unroll 4
        for (int s = 0; s < smax; s++)
            t += src[(size_t)s * Dd];
        as[b][j] = bf16r(t);
    }
    __syncthreads();

    float4 acc[Bb];
#pragma unroll
    for (int b = 0; b < Bb; b++) acc[b] = make_float4(0.f, 0.f, 0.f, 0.f);

#pragma unroll 4
    for (int j = 0; j < 16; j++) {
#pragma unroll
        for (int b = 0; b < Bb; b++) {
            float av = as[b][j];
            acc[b].x = fmaf(av, w[j].x, acc[b].x);
            acc[b].y = fmaf(av, w[j].y, acc[b].y);
            acc[b].z = fmaf(av, w[j].z, acc[b].z);
            acc[b].w = fmaf(av, w[j].w, acc[b].w);
        }
    }
#pragma unroll
    for (int b = 0; b < Bb; b++)
        ((float4*)(g_out_partial + ((size_t)hc * Bb + b) * Ff))[tid] = acc[b];
}

// ---------------------------------------------------------------------------
// K6: outproj reduce; bo prefetched pre-sync (input-only)
// ---------------------------------------------------------------------------
__global__ __launch_bounds__(256) void outproj_reduce_kernel(const float* __restrict__ bo,
                                                             float* __restrict__ out) {
    int i = blockIdx.x * 256 + threadIdx.x;   // < B*F = 16384
    int f = i & (Ff - 1);
    float s = __ldg(bo + f);                  // pre-sync input load
    cudaGridDependencySynchronize();
    if (i < Bb * Ff) {
#pragma unroll 8
        for (int c = 0; c < OCH; c++)
            s += g_out_partial[(size_t)c * Bb * Ff + i];
        out[OFF_Y + i] = s;
    }
}

// ---------------------------------------------------------------------------
// Host: PDL-chained launches (kernels 2..6 use programmatic stream serialization)
// ---------------------------------------------------------------------------
template <typename K, typename... Args>
static void launch_pdl(K kernel, int grid, int block, Args... args) {
    cudaLaunchAttribute attr[1];
    attr[0].id = cudaLaunchAttributeProgrammaticStreamSerialization;
    attr[0].val.programmaticStreamSerializationAllowed = 1;
    cudaLaunchConfig_t cfg = {};
    cfg.gridDim = dim3(grid, 1, 1);
    cfg.blockDim = dim3(block, 1, 1);
    cfg.dynamicSmemBytes = 0;
    cfg.stream = 0;
    cfg.attrs = attr;
    cfg.numAttrs = 1;
    cudaLaunchKernelEx(&cfg, kernel, args...);
}

extern "C" void kernel_launch(void* const* d_in, const int* in_sizes, int n_in,
                              void* d_out, int out_size) {
    const float* x    = (const float*)d_in[0];
    const float* kvk  = (const float*)d_in[1];
    const float* kvv  = (const float*)d_in[2];
    const int*   kidx = (const int*)  d_in[3];
    const float* Wq   = (const float*)d_in[4];
    const float* bq   = (const float*)d_in[5];
    const float* Wk   = (const float*)d_in[6];
    const float* bk   = (const float*)d_in[7];
    const float* Wv   = (const float*)d_in[8];
    const float* bv   = (const float*)d_in[9];
    const float* Wo   = (const float*)d_in[10];
    const float* bo   = (const float*)d_in[11];
    float* out = (float*)d_out;

    proj_partial_kernel<<<3 * FCH, 256>>>(x, Wq, Wk, Wv);                       // K1
    launch_pdl(proj_reduce_kernel, 192, 256, bq, bk, bv, kidx, out);            // K2
    launch_pdl(copyk_logits_kernel, Bb * CPB, 256, kvk, kidx, out);             // K3
    launch_pdl(copyv_av_kernel, Bb * CPB, 256, kvv, kidx, out);                 // K4 <- ncu target
    launch_pdl(outproj_partial_kernel, OCH, 256, Wo, kidx);                     // K5
    launch_pdl(outproj_reduce_kernel, 64, 256, bo, out);                        // K6
}